// round 6
// baseline (speedup 1.0000x reference)
#include <cuda_runtime.h>
#include <math.h>
#include <stdint.h>

#define B_   2
#define T_   2048
#define D_   512
#define H_   8
#define HD_  64
#define QKV3 (3 * D_)   // 1536
#define NROW (B_ * T_)  // 4096

__device__ float g_qkv[B_ * T_ * QKV3];
__device__ float g_attn[B_ * T_ * D_];

// ---------------------------------------------------------------------------
// TF32 GEMM v3: block 256x128, 8 warps (4x2) of 64x64, BK=16, double-buffered.
// Smem pair-interleaved: (k, k+4) contiguous -> all fragment loads are LDS.64.
// ---------------------------------------------------------------------------
#define MPA 260              // uint2 stride per k-pair row (A), 2*260 % 32 == 8
#define MPW 132              // uint2 stride per k-pair row (W)
#define ASZ (8 * MPA)        // uint2 per A buffer
#define WSZ (8 * MPW)        // uint2 per W buffer
#define GEMM_SMEM ((2 * ASZ + 2 * WSZ) * 8)   // bytes

__device__ __forceinline__ uint32_t f2tf32(float x) {
    uint32_t u;
    asm("cvt.rna.tf32.f32 %0, %1;" : "=r"(u) : "f"(x));
    return u;
}

__global__ __launch_bounds__(256)
void gemm_tf32_v3(const float* __restrict__ A, const float* __restrict__ W,
                  const float* __restrict__ bias, float* __restrict__ C,
                  int N, int M, int K)
{
    extern __shared__ uint2 sm[];
    uint2* Asm = sm;            // [2][ASZ]
    uint2* Wsm = sm + 2 * ASZ;  // [2][WSZ]

    const int tid  = threadIdx.x;
    const int warp = tid >> 5;
    const int lane = tid & 31;
    const int g    = lane >> 2;
    const int t4   = lane & 3;

    const int n0 = blockIdx.y * 256;
    const int m0 = blockIdx.x * 128;
    const int wr = (warp & 3) * 64;    // 4 row warps
    const int wc = (warp >> 2) * 64;   // 2 col warps

    const float* Arow = A + (size_t)(n0 + tid) * K;
    const int mw  = tid >> 1;
    const int g2l = tid & 1;
    const float* Wrow = W + (size_t)(m0 + mw) * K + g2l * 8;

    float c[4][8][4];
#pragma unroll
    for (int mi = 0; mi < 4; mi++)
#pragma unroll
        for (int ni = 0; ni < 8; ni++)
#pragma unroll
            for (int q = 0; q < 4; q++) c[mi][ni][q] = 0.f;

    float4 a0v, a1v, a2v, a3v, w0v, w1v;

#define LD_TILE(koff)                                  \
    a0v = *(const float4*)(Arow + (koff));             \
    a1v = *(const float4*)(Arow + (koff) + 4);         \
    a2v = *(const float4*)(Arow + (koff) + 8);         \
    a3v = *(const float4*)(Arow + (koff) + 12);        \
    w0v = *(const float4*)(Wrow + (koff));             \
    w1v = *(const float4*)(Wrow + (koff) + 4);

#define ST_TILE(buf)                                                        \
    {                                                                       \
        uint2* da = Asm + (buf) * ASZ + tid;                                \
        da[0*MPA] = make_uint2(f2tf32(a0v.x), f2tf32(a1v.x));               \
        da[1*MPA] = make_uint2(f2tf32(a0v.y), f2tf32(a1v.y));               \
        da[2*MPA] = make_uint2(f2tf32(a0v.z), f2tf32(a1v.z));               \
        da[3*MPA] = make_uint2(f2tf32(a0v.w), f2tf32(a1v.w));               \
        da[4*MPA] = make_uint2(f2tf32(a2v.x), f2tf32(a3v.x));               \
        da[5*MPA] = make_uint2(f2tf32(a2v.y), f2tf32(a3v.y));               \
        da[6*MPA] = make_uint2(f2tf32(a2v.z), f2tf32(a3v.z));               \
        da[7*MPA] = make_uint2(f2tf32(a2v.w), f2tf32(a3v.w));               \
        uint2* dw = Wsm + (buf) * WSZ + g2l * 4 * MPW + mw;                 \
        dw[0*MPW] = make_uint2(f2tf32(w0v.x), f2tf32(w1v.x));               \
        dw[1*MPW] = make_uint2(f2tf32(w0v.y), f2tf32(w1v.y));               \
        dw[2*MPW] = make_uint2(f2tf32(w0v.z), f2tf32(w1v.z));               \
        dw[3*MPW] = make_uint2(f2tf32(w0v.w), f2tf32(w1v.w));               \
    }

    LD_TILE(0);
    ST_TILE(0);
    __syncthreads();

    const int NT = K / 16;
    for (int it = 0; it < NT; it++) {
        if (it + 1 < NT) { LD_TILE((it + 1) * 16); }
        const int buf = it & 1;
#pragma unroll
        for (int g2 = 0; g2 < 2; g2++) {
            const uint2* ab = Asm + buf * ASZ + (g2 * 4 + t4) * MPA;
            const uint2* wb = Wsm + buf * WSZ + (g2 * 4 + t4) * MPW;
            uint2 bf[8];
#pragma unroll
            for (int ni = 0; ni < 8; ni++)
                bf[ni] = wb[wc + ni * 8 + g];
#pragma unroll
            for (int mi = 0; mi < 4; mi++) {
                uint2 aL = ab[wr + mi * 16 + g];
                uint2 aH = ab[wr + mi * 16 + g + 8];
#pragma unroll
                for (int ni = 0; ni < 8; ni++) {
                    asm volatile(
                        "mma.sync.aligned.m16n8k8.row.col.f32.tf32.tf32.f32 "
                        "{%0,%1,%2,%3}, {%4,%5,%6,%7}, {%8,%9}, {%0,%1,%2,%3};"
                        : "+f"(c[mi][ni][0]), "+f"(c[mi][ni][1]),
                          "+f"(c[mi][ni][2]), "+f"(c[mi][ni][3])
                        : "r"(aL.x), "r"(aH.x), "r"(aL.y), "r"(aH.y),
                          "r"(bf[ni].x), "r"(bf[ni].y));
                }
            }
        }
        if (it + 1 < NT) {
            __syncthreads();
            ST_TILE((it + 1) & 1);
            __syncthreads();
        }
    }

#pragma unroll
    for (int mi = 0; mi < 4; mi++) {
        int row_a = n0 + wr + mi * 16 + g;
        int row_b = row_a + 8;
#pragma unroll
        for (int ni = 0; ni < 8; ni++) {
            int col = m0 + wc + ni * 8 + 2 * t4;
            float bx = bias[col], by = bias[col + 1];
            *(float2*)(C + (size_t)row_a * M + col) =
                make_float2(c[mi][ni][0] + bx, c[mi][ni][1] + by);
            *(float2*)(C + (size_t)row_b * M + col) =
                make_float2(c[mi][ni][2] + bx, c[mi][ni][3] + by);
        }
    }
#undef LD_TILE
#undef ST_TILE
}

// ---------------------------------------------------------------------------
// Residue-class attention, 4 key-phase warps per query.
// Block = 1024 threads = 8 queries x 4 phases. 64-key stages in smem.
// ---------------------------------------------------------------------------
__global__ __launch_bounds__(1024)
void attn_class4(const int* __restrict__ periods)
{
    const int bh = blockIdx.y;
    const int b  = bh >> 3;
    const int h  = bh & 7;
    int p = periods[bh];
    if (p < 1) p = 1;

    const int x    = blockIdx.x;
    const int r    = x % p;
    const int tile = x / p;
    const int c0   = tile * 8;
    if (r + c0 * p > T_ - 1) return;

    const int tid  = threadIdx.x;
    const int warp = tid >> 5;
    const int lane = tid & 31;

    const int L    = (T_ - 1 - r) / p + 1;
    const int cmax = min(c0 + 7, L - 1);
    const int nch  = cmax / 32 + 1;

    __shared__ float Ks[64 * 65];
    __shared__ float Vs[64 * 65];
    __shared__ float Qs[8][64];
    __shared__ float Cmb[8][3][66];

    const float* base = g_qkv + (size_t)b * T_ * QKV3;

    if (tid < 512) {
        int qi = tid >> 6, d = tid & 63;
        int cq = c0 + qi;
        float qv = 0.f;
        if (cq <= cmax) {
            int iq = r + cq * p;
            qv = base[(size_t)iq * QKV3 + h * HD_ + d] * 0.125f;
        }
        Qs[qi][d] = qv;
    }

    const int q     = warp & 7;
    const int phase = warp >> 3;     // 0..3
    const int cq    = c0 + q;
    const bool qvalid = (cq <= cmax);

    float m_run = -1e30f, l_run = 0.f;
    float accA = 0.f, accB = 0.f;

    const int niter = (nch + 1) >> 1;
    for (int t = 0; t < niter; t++) {
        __syncthreads();
        {   // stage keys [64t, 64t+64): 16 threads per row
            int row = tid >> 4;
            int wp  = tid & 15;
            int mg  = t * 64 + row;
            if (mg <= cmax) {
                int ik = r + mg * p;
                const float* src = base + (size_t)ik * QKV3 + D_ + h * HD_;
                if (wp < 8) {
                    int cb = wp * 8;
                    float4 k0 = *(const float4*)(src + cb);
                    float4 k1 = *(const float4*)(src + cb + 4);
                    float* kd = &Ks[row * 65 + cb];
                    kd[0]=k0.x; kd[1]=k0.y; kd[2]=k0.z; kd[3]=k0.w;
                    kd[4]=k1.x; kd[5]=k1.y; kd[6]=k1.z; kd[7]=k1.w;
                } else {
                    int cb = (wp - 8) * 8;
                    float4 v0 = *(const float4*)(src + D_ + cb);
                    float4 v1 = *(const float4*)(src + D_ + cb + 4);
                    float* vd = &Vs[row * 65 + cb];
                    vd[0]=v0.x; vd[1]=v0.y; vd[2]=v0.z; vd[3]=v0.w;
                    vd[4]=v1.x; vd[5]=v1.y; vd[6]=v1.z; vd[7]=v1.w;
                }
            }
        }
        __syncthreads();

        const int ch0 = 2 * t;
        int ch = -1;
        if ((ch0 & 3) == phase) ch = ch0;
        else if (((ch0 + 1) & 3) == phase) ch = ch0 + 1;

        if (qvalid && ch >= 0 && ch < nch && ch * 32 <= cq) {
            const int rb = (ch & 1) * 32;
            float s = -1e30f;
            if (ch * 32 + lane <= cq) {
                const float* kr2 = &Ks[(rb + lane) * 65];
                const float* qp  = Qs[q];
                float d0 = 0.f, d1 = 0.f, d2 = 0.f, d3 = 0.f;
#pragma unroll
                for (int d = 0; d < 64; d += 4) {
                    d0 = fmaf(qp[d],     kr2[d],     d0);
                    d1 = fmaf(qp[d + 1], kr2[d + 1], d1);
                    d2 = fmaf(qp[d + 2], kr2[d + 2], d2);
                    d3 = fmaf(qp[d + 3], kr2[d + 3], d3);
                }
                s = (d0 + d1) + (d2 + d3);
            }
            float cm = s;
#pragma unroll
            for (int o = 16; o > 0; o >>= 1)
                cm = fmaxf(cm, __shfl_xor_sync(0xffffffffu, cm, o));
            float nm   = fmaxf(m_run, cm);
            float corr = __expf(m_run - nm);
            float pe   = __expf(s - nm);
            float cs = pe;
#pragma unroll
            for (int o = 16; o > 0; o >>= 1)
                cs += __shfl_xor_sync(0xffffffffu, cs, o);
            l_run = l_run * corr + cs;

            float a0 = 0.f, a1 = 0.f, b0 = 0.f, b1 = 0.f;
#pragma unroll 4
            for (int j = 0; j < 32; j += 2) {
                float pj0 = __shfl_sync(0xffffffffu, pe, j);
                float pj1 = __shfl_sync(0xffffffffu, pe, j + 1);
                const float* v0 = &Vs[(rb + j) * 65];
                const float* v1 = &Vs[(rb + j + 1) * 65];
                a0 = fmaf(pj0, v0[lane],      a0);
                b0 = fmaf(pj0, v0[32 + lane], b0);
                a1 = fmaf(pj1, v1[lane],      a1);
                b1 = fmaf(pj1, v1[32 + lane], b1);
            }
            accA = fmaf(accA, corr, a0 + a1);
            accB = fmaf(accB, corr, b0 + b1);
            m_run = nm;
        }
    }

    __syncthreads();
    if (qvalid && phase > 0) {
        if (lane == 0) { Cmb[q][phase - 1][0] = m_run; Cmb[q][phase - 1][1] = l_run; }
        Cmb[q][phase - 1][2 + lane]  = accA;
        Cmb[q][phase - 1][34 + lane] = accB;
    }
    __syncthreads();
    if (qvalid && phase == 0) {
        float M = m_run, Lq = l_run, oA = accA, oB = accB;
#pragma unroll
        for (int e = 0; e < 3; e++) {
            float mb = Cmb[q][e][0], lb = Cmb[q][e][1];
            float nm = fmaxf(M, mb);
            float ca = __expf(M - nm), cb2 = __expf(mb - nm);
            Lq = Lq * ca + lb * cb2;
            oA = oA * ca + Cmb[q][e][2 + lane]  * cb2;
            oB = oB * ca + Cmb[q][e][34 + lane] * cb2;
            M = nm;
        }
        float inv = 1.f / Lq;
        int iq = r + cq * p;
        float* orow = g_attn + (size_t)(b * T_ + iq) * D_ + h * HD_;
        orow[lane]      = oA * inv;
        orow[lane + 32] = oB * inv;
    }
}

// ---------------------------------------------------------------------------
extern "C" void kernel_launch(void* const* d_in, const int* in_sizes, int n_in,
                              void* d_out, int out_size)
{
    const float* x      = (const float*)d_in[0];
    const int*   periods= (const int*)  d_in[1];
    const float* w_qkv  = (const float*)d_in[2];
    const float* b_qkv  = (const float*)d_in[3];
    const float* w_out  = (const float*)d_in[4];
    const float* b_out  = (const float*)d_in[5];
    float*       out    = (float*)d_out;

    float* qkv_ptr = nullptr;
    float* attn_ptr = nullptr;
    cudaGetSymbolAddress((void**)&qkv_ptr, g_qkv);
    cudaGetSymbolAddress((void**)&attn_ptr, g_attn);

    static bool attr_set = false;
    if (!attr_set) {
        cudaFuncSetAttribute(gemm_tf32_v3,
                             cudaFuncAttributeMaxDynamicSharedMemorySize,
                             GEMM_SMEM);
        attr_set = true;
    }

    {   // QKV projection: (4096 x 1536)
        dim3 grid(QKV3 / 128, NROW / 256);
        gemm_tf32_v3<<<grid, 256, GEMM_SMEM>>>(x, w_qkv, b_qkv, qkv_ptr,
                                               NROW, QKV3, D_);
    }
    {   // periodic-causal attention
        dim3 grid(320, B_ * H_);
        attn_class4<<<grid, 1024>>>(periods);
    }
    {   // output projection: (4096 x 512)
        dim3 grid(D_ / 128, NROW / 256);
        gemm_tf32_v3<<<grid, 256, GEMM_SMEM>>>(attn_ptr, w_out, b_out, out,
                                               NROW, D_, D_);
    }
}

// round 7
// speedup vs baseline: 1.4201x; 1.4201x over previous
#include <cuda_runtime.h>
#include <math.h>
#include <stdint.h>

#define B_   2
#define T_   2048
#define D_   512
#define H_   8
#define HD_  64
#define QKV3 (3 * D_)   // 1536
#define NROW (B_ * T_)  // 4096

__device__ float g_qkv[B_ * T_ * QKV3];
__device__ float g_attn[B_ * T_ * D_];

// ---------------------------------------------------------------------------
// TF32 GEMM v4: round-3 shape (block 128x128, BK=16, 256 thr, 8 warps 64x32),
// double-buffered, with pair-interleaved uint2 smem -> all frag loads LDS.64.
// Pair-row kp = (k>=8)*4 + (k&3); uint2 at [kp*132 + row] = {tf32(k), tf32(k+4)}.
// ---------------------------------------------------------------------------
#define MP  132              // uint2 stride per pair-row (128 + 4 pad)
#define BSZ (8 * MP)         // uint2 per (A or W) buffer

__device__ __forceinline__ uint32_t f2tf32(float x) {
    uint32_t u;
    asm("cvt.rna.tf32.f32 %0, %1;" : "=r"(u) : "f"(x));
    return u;
}

__global__ __launch_bounds__(256)
void gemm_tf32_v4(const float* __restrict__ A, const float* __restrict__ W,
                  const float* __restrict__ bias, float* __restrict__ C,
                  int N, int M, int K)
{
    __shared__ uint2 Asm[2][BSZ];
    __shared__ uint2 Wsm[2][BSZ];

    const int tid  = threadIdx.x;
    const int warp = tid >> 5;
    const int lane = tid & 31;
    const int g    = lane >> 2;   // 0..7
    const int t4   = lane & 3;    // 0..3

    const int n0 = blockIdx.y * 128;
    const int m0 = blockIdx.x * 128;
    const int r0 = (warp >> 2) * 64;   // 0 / 64
    const int c0 = (warp & 3) * 32;    // 0,32,64,96

    const int lrow = tid >> 1;         // 0..127
    const int lg2  = tid & 1;          // k-half: 0 -> k0..7, 1 -> k8..15
    const float* Arow = A + (size_t)(n0 + lrow) * K + lg2 * 8;
    const float* Wrow = W + (size_t)(m0 + lrow) * K + lg2 * 8;

    float c[4][4][4];
#pragma unroll
    for (int mi = 0; mi < 4; mi++)
#pragma unroll
        for (int ni = 0; ni < 4; ni++)
#pragma unroll
            for (int q = 0; q < 4; q++) c[mi][ni][q] = 0.f;

    float4 av0, av1, wv0, wv1;

#define LD_TILE(koff)                              \
    av0 = *(const float4*)(Arow + (koff));         \
    av1 = *(const float4*)(Arow + (koff) + 4);     \
    wv0 = *(const float4*)(Wrow + (koff));         \
    wv1 = *(const float4*)(Wrow + (koff) + 4);

#define ST_TILE(buf)                                                  \
    {                                                                 \
        uint2* da = &Asm[(buf)][lg2 * 4 * MP + lrow];                 \
        da[0*MP] = make_uint2(f2tf32(av0.x), f2tf32(av1.x));          \
        da[1*MP] = make_uint2(f2tf32(av0.y), f2tf32(av1.y));          \
        da[2*MP] = make_uint2(f2tf32(av0.z), f2tf32(av1.z));          \
        da[3*MP] = make_uint2(f2tf32(av0.w), f2tf32(av1.w));          \
        uint2* dw = &Wsm[(buf)][lg2 * 4 * MP + lrow];                 \
        dw[0*MP] = make_uint2(f2tf32(wv0.x), f2tf32(wv1.x));          \
        dw[1*MP] = make_uint2(f2tf32(wv0.y), f2tf32(wv1.y));          \
        dw[2*MP] = make_uint2(f2tf32(wv0.z), f2tf32(wv1.z));          \
        dw[3*MP] = make_uint2(f2tf32(wv0.w), f2tf32(wv1.w));          \
    }

    LD_TILE(0);
    ST_TILE(0);
    __syncthreads();

    const int NT = K / 16;
    for (int it = 0; it < NT; it++) {
        if (it + 1 < NT) { LD_TILE((it + 1) * 16); }
        const int buf = it & 1;
#pragma unroll
        for (int g2 = 0; g2 < 2; g2++) {
            const uint2* ab = &Asm[buf][(g2 * 4 + t4) * MP];
            const uint2* wb = &Wsm[buf][(g2 * 4 + t4) * MP];
            uint2 bf[4];
#pragma unroll
            for (int ni = 0; ni < 4; ni++)
                bf[ni] = wb[c0 + ni * 8 + g];
#pragma unroll
            for (int mi = 0; mi < 4; mi++) {
                uint2 aL = ab[r0 + mi * 16 + g];
                uint2 aH = ab[r0 + mi * 16 + g + 8];
#pragma unroll
                for (int ni = 0; ni < 4; ni++) {
                    asm volatile(
                        "mma.sync.aligned.m16n8k8.row.col.f32.tf32.tf32.f32 "
                        "{%0,%1,%2,%3}, {%4,%5,%6,%7}, {%8,%9}, {%0,%1,%2,%3};"
                        : "+f"(c[mi][ni][0]), "+f"(c[mi][ni][1]),
                          "+f"(c[mi][ni][2]), "+f"(c[mi][ni][3])
                        : "r"(aL.x), "r"(aH.x), "r"(aL.y), "r"(aH.y),
                          "r"(bf[ni].x), "r"(bf[ni].y));
                }
            }
        }
        if (it + 1 < NT) {
            __syncthreads();
            ST_TILE((it + 1) & 1);
            __syncthreads();
        }
    }

#pragma unroll
    for (int mi = 0; mi < 4; mi++) {
        int row_a = n0 + r0 + mi * 16 + g;
        int row_b = row_a + 8;
#pragma unroll
        for (int ni = 0; ni < 4; ni++) {
            int col = m0 + c0 + ni * 8 + 2 * t4;
            float bx = bias[col], by = bias[col + 1];
            *(float2*)(C + (size_t)row_a * M + col) =
                make_float2(c[mi][ni][0] + bx, c[mi][ni][1] + by);
            *(float2*)(C + (size_t)row_b * M + col) =
                make_float2(c[mi][ni][2] + bx, c[mi][ni][3] + by);
        }
    }
#undef LD_TILE
#undef ST_TILE
}

// ---------------------------------------------------------------------------
// Residue-class attention (round-3 proven version).
// Block = (bh, r, 8-query tile). 64-key smem stages; 2 warps per query
// (even/odd 32-key chunks), lane = key, combine halves at the end.
// ---------------------------------------------------------------------------
#define AQ 8
__global__ __launch_bounds__(512)
void attn_class_kernel(const int* __restrict__ periods)
{
    const int bh = blockIdx.y;
    const int b  = bh >> 3;
    const int h  = bh & 7;
    int p = periods[bh];
    if (p < 1) p = 1;

    const int x    = blockIdx.x;
    const int r    = x % p;
    const int tile = x / p;
    const int c0   = tile * AQ;
    if (r + c0 * p > T_ - 1) return;

    const int tid  = threadIdx.x;
    const int warp = tid >> 5;
    const int lane = tid & 31;

    const int L    = (T_ - 1 - r) / p + 1;
    const int cmax = min(c0 + AQ - 1, L - 1);
    const int nch  = cmax / 32 + 1;

    __shared__ float Ks[64 * 65];
    __shared__ float Vs[64 * 65];
    __shared__ float Qs[AQ][64];
    __shared__ float Cmb[AQ][66];

    const float* base = g_qkv + (size_t)b * T_ * QKV3;

    {
        int qi = tid >> 6, d = tid & 63;
        int cq = c0 + qi;
        float qv = 0.f;
        if (cq <= cmax) {
            int iq = r + cq * p;
            qv = base[(size_t)iq * QKV3 + h * HD_ + d] * 0.125f;
        }
        Qs[qi][d] = qv;
    }

    const int q    = warp & 7;
    const int half = warp >> 3;
    const int cq   = c0 + q;
    const bool qvalid = (cq <= cmax);

    float m_run = -1e30f, l_run = 0.f;
    float accA = 0.f, accB = 0.f;

    const int niter = (nch + 1) >> 1;
    for (int t = 0; t < niter; t++) {
        __syncthreads();
        {
            int row = tid >> 3;
            int cb  = (tid & 7) * 8;
            int mg  = t * 64 + row;
            if (mg <= cmax) {
                int ik = r + mg * p;
                const float* kr = base + (size_t)ik * QKV3 + D_ + h * HD_ + cb;
                float4 k0 = *(const float4*)(kr);
                float4 k1 = *(const float4*)(kr + 4);
                float4 v0 = *(const float4*)(kr + D_);
                float4 v1 = *(const float4*)(kr + D_ + 4);
                float* kd = &Ks[row * 65 + cb];
                kd[0]=k0.x; kd[1]=k0.y; kd[2]=k0.z; kd[3]=k0.w;
                kd[4]=k1.x; kd[5]=k1.y; kd[6]=k1.z; kd[7]=k1.w;
                float* vd = &Vs[row * 65 + cb];
                vd[0]=v0.x; vd[1]=v0.y; vd[2]=v0.z; vd[3]=v0.w;
                vd[4]=v1.x; vd[5]=v1.y; vd[6]=v1.z; vd[7]=v1.w;
            }
        }
        __syncthreads();

        const int ch = 2 * t + half;
        const int m0 = ch * 32;
        if (qvalid && ch < nch && m0 <= cq) {
            const int rb = half * 32;
            float s = -1e30f;
            if (m0 + lane <= cq) {
                const float* kr2 = &Ks[(rb + lane) * 65];
                const float* qp  = Qs[q];
                float d0 = 0.f, d1 = 0.f, d2 = 0.f, d3 = 0.f;
#pragma unroll
                for (int d = 0; d < 64; d += 4) {
                    d0 = fmaf(qp[d],     kr2[d],     d0);
                    d1 = fmaf(qp[d + 1], kr2[d + 1], d1);
                    d2 = fmaf(qp[d + 2], kr2[d + 2], d2);
                    d3 = fmaf(qp[d + 3], kr2[d + 3], d3);
                }
                s = (d0 + d1) + (d2 + d3);
            }
            float cm = s;
#pragma unroll
            for (int o = 16; o > 0; o >>= 1)
                cm = fmaxf(cm, __shfl_xor_sync(0xffffffffu, cm, o));
            float nm   = fmaxf(m_run, cm);
            float corr = __expf(m_run - nm);
            float pe   = __expf(s - nm);
            float cs = pe;
#pragma unroll
            for (int o = 16; o > 0; o >>= 1)
                cs += __shfl_xor_sync(0xffffffffu, cs, o);
            l_run = l_run * corr + cs;

            float a0 = 0.f, a1 = 0.f, b0 = 0.f, b1 = 0.f;
#pragma unroll 4
            for (int j = 0; j < 32; j += 2) {
                float pj0 = __shfl_sync(0xffffffffu, pe, j);
                float pj1 = __shfl_sync(0xffffffffu, pe, j + 1);
                const float* v0 = &Vs[(rb + j) * 65];
                const float* v1 = &Vs[(rb + j + 1) * 65];
                a0 = fmaf(pj0, v0[lane],      a0);
                b0 = fmaf(pj0, v0[32 + lane], b0);
                a1 = fmaf(pj1, v1[lane],      a1);
                b1 = fmaf(pj1, v1[32 + lane], b1);
            }
            accA = fmaf(accA, corr, a0 + a1);
            accB = fmaf(accB, corr, b0 + b1);
            m_run = nm;
        }
    }

    __syncthreads();
    if (half == 1 && qvalid) {
        if (lane == 0) { Cmb[q][0] = m_run; Cmb[q][1] = l_run; }
        Cmb[q][2 + lane]      = accA;
        Cmb[q][2 + 32 + lane] = accB;
    }
    __syncthreads();
    if (half == 0 && qvalid) {
        float mb = Cmb[q][0], lb = Cmb[q][1];
        float nm = fmaxf(m_run, mb);
        float ca = __expf(m_run - nm), cb = __expf(mb - nm);
        float l  = l_run * ca + lb * cb;
        float oA = accA * ca + Cmb[q][2 + lane] * cb;
        float oB = accB * ca + Cmb[q][2 + 32 + lane] * cb;
        float inv = 1.f / l;
        int iq = r + cq * p;
        float* orow = g_attn + (size_t)(b * T_ + iq) * D_ + h * HD_;
        orow[lane]      = oA * inv;
        orow[lane + 32] = oB * inv;
    }
}

// ---------------------------------------------------------------------------
extern "C" void kernel_launch(void* const* d_in, const int* in_sizes, int n_in,
                              void* d_out, int out_size)
{
    const float* x      = (const float*)d_in[0];
    const int*   periods= (const int*)  d_in[1];
    const float* w_qkv  = (const float*)d_in[2];
    const float* b_qkv  = (const float*)d_in[3];
    const float* w_out  = (const float*)d_in[4];
    const float* b_out  = (const float*)d_in[5];
    float*       out    = (float*)d_out;

    float* qkv_ptr = nullptr;
    float* attn_ptr = nullptr;
    cudaGetSymbolAddress((void**)&qkv_ptr, g_qkv);
    cudaGetSymbolAddress((void**)&attn_ptr, g_attn);

    {   // QKV projection: (4096 x 1536)
        dim3 grid(QKV3 / 128, NROW / 128);
        gemm_tf32_v4<<<grid, 256>>>(x, w_qkv, b_qkv, qkv_ptr, NROW, QKV3, D_);
    }
    {   // periodic-causal attention (residue classes)
        dim3 grid(320, B_ * H_);
        attn_class_kernel<<<grid, 512>>>(periods);
    }
    {   // output projection: (4096 x 512)
        dim3 grid(D_ / 128, NROW / 128);
        gemm_tf32_v4<<<grid, 256>>>(attn_ptr, w_out, b_out, out, NROW, D_, D_);
    }
}